// round 13
// baseline (speedup 1.0000x reference)
#include <cuda_runtime.h>
#include <cuda_fp16.h>
#include <cstdint>

// Hopf oscillator CPG step, reformulated:
//   sin(psi_j - psi_i - phi_ij) = (s_j c_i - c_j s_i)cosφ - (c_j c_i + s_j s_i)sinφ
// A_ij = w_zd cosφ_zd, B_ij = w_zd sinφ_zd, x_j = r_j s_j, y_j = r_j c_j:
//   coupling_i = c_i*(A x - B y)_i - s_i*(A y + B x)_i
// R13 = R12 (21.0us) refinements:
//  * matrix packed as uint2 {half2{A,B}, half2{B,A}} -> ONE LDS.64 feeds both
//    accP += {A,B}⊙{x,y} = {ΣAx,ΣBy} and accQ += {B,A}⊙{x,y} = {ΣBx,ΣAy};
//    sYX mirror buffer deleted (one broadcast LDS.128 per quad-j instead of two)
//  * all 8 rows' LDGs hoisted up front (single L2 latency exposure, MLP=24),
//    both quads staged, single __syncwarp
//  * launch_bounds(256,4) for the higher register count (occ proven non-binding)

#define PI2F 6.28318530717958647692f

__device__ uint2 gABBA[1024];   // [j*32 + i] = {half2{A,B}, half2{B,A}} (pre-transposed)
__device__ float gTPV[32];      // 2*pi*V_MAX*sigmoid(v)
__device__ float gBA[32];       // B_MAX*sigmoid(b)
__device__ float gCA[32];       // C_MAX*sigmoid(c)

__device__ __forceinline__ float fsigmoid(float x) {
    return 1.0f / (1.0f + __expf(-x));
}

__global__ void prep_kernel(const float* __restrict__ v, const float* __restrict__ b,
                            const float* __restrict__ c, const float* __restrict__ w,
                            const float* __restrict__ phi) {
    int m = blockIdx.x * 128 + threadIdx.x;   // 0..1023, m = i*32 + j
    float A = 0.0f, Bv = 0.0f;
    if (m % 33 != 0) {              // zero-diag: diagonal iff m % 33 == 0
        int kk = m / 33;            // 0..30
        int jj = m % 33 - 1;        // 0..31
        float wa = fsigmoid(w[kk * 32 + jj]);           // W_MAX = 1
        float pa = PI2F * fsigmoid(phi[kk * 32 + jj]);  // PHI_MAX = 2*pi
        float sp, cp;
        __sincosf(pa, &sp, &cp);
        A  = wa * cp;
        Bv = wa * sp;
    }
    __half2 ab = __floats2half2_rn(A, Bv);
    __half2 ba = __floats2half2_rn(Bv, A);
    gABBA[(m & 31) * 32 + (m >> 5)] =
        make_uint2(*reinterpret_cast<uint32_t*>(&ab), *reinterpret_cast<uint32_t*>(&ba));
    if (m < 32) {
        gTPV[m] = (PI2F * 5.0f) * fsigmoid(v[m]);
        gBA[m]  = 2.0f  * fsigmoid(b[m]);
        gCA[m]  = 10.0f * fsigmoid(c[m]);
    }
}

// ---------------- hot kernel: full 64-row tiles only, no guards ----------------
__global__ __launch_bounds__(256, 4)
void hopf_kernel(const float* __restrict__ in, float* __restrict__ out) {
    const int tid  = threadIdx.x;
    const int lane = tid & 31;          // oscillator index i
    const int wib  = tid >> 5;          // warp in block (0..7)

    __shared__ uint2 sABBA[1024];       // [j*32 + i] -> LDS.64, conflict-free
    __shared__ uint4 sXY[8][2][32];     // [warp][quad][j] = half2{x,y} rows 0..3

    // coalesced L2->smem copy of the prebuilt matrix (8KB, 2 float4/thread)
    {
        const float4* src = reinterpret_cast<const float4*>(gABBA);
        float4*       dst = reinterpret_cast<float4*>(sABBA);
        dst[tid]       = src[tid];
        dst[tid + 256] = src[tid + 256];
    }

    const float tpv = gTPV[lane];
    const float ba  = gBA[lane];
    const float ca  = gCA[lane];

    __syncthreads();

    const int rowBase = (blockIdx.x * 8 + wib) * 8;   // 8 rows per warp

    // ---- hoisted loads: all 8 rows, back-to-back LDGs (MLP=24) ----
    float psi[8], rr[8], rd[8];
    #pragma unroll
    for (int t = 0; t < 8; t++) {
        const float* rp = in + (size_t)(rowBase + t) * 96;
        psi[t] = rp[lane];
        rr[t]  = rp[32 + lane];
        rd[t]  = rp[64 + lane];
    }

    // ---- prologue: sincos, xy staging (both quads), rd/rdd stores ----
    float sv[8], cv[8];
    uint4 xy0, xy1;
    #pragma unroll
    for (int t = 0; t < 8; t++) {
        __sincosf(psi[t], &sv[t], &cv[t]);
        __half2 h = __floats2half2_rn(rr[t] * sv[t], rr[t] * cv[t]);   // {x,y}
        if (t < 4) reinterpret_cast<__half2*>(&xy0)[t]     = h;
        else       reinterpret_cast<__half2*>(&xy1)[t - 4] = h;
        float rdd = ca * (0.25f * ca * (ba - rr[t]) - rd[t]);
        float* op = out + (size_t)(rowBase + t) * 96;
        op[32 + lane] = rd[t];
        op[64 + lane] = rdd;
    }
    sXY[wib][0][lane] = xy0;
    sXY[wib][1][lane] = xy1;
    __syncwarp();

    #pragma unroll
    for (int q = 0; q < 2; q++) {
        // split half2 accumulators: [t] over 4 rows; 0 = j<16, 1 = j>=16
        __half2 z = __floats2half2_rn(0.0f, 0.0f);
        __half2 aP0[4] = {z,z,z,z}, aP1[4] = {z,z,z,z};
        __half2 aQ0[4] = {z,z,z,z}, aQ1[4] = {z,z,z,z};

        #pragma unroll
        for (int j = 0; j < 16; j++) {
            uint2 m = sABBA[j * 32 + lane];              // LDS.64 {AB, BA}
            __half2 ab = *reinterpret_cast<__half2*>(&m.x);
            __half2 ba2 = *reinterpret_cast<__half2*>(&m.y);
            uint4 pxy = sXY[wib][q][j];                  // broadcast LDS.128
            const __half2* hx = reinterpret_cast<const __half2*>(&pxy);
            #pragma unroll
            for (int t = 0; t < 4; t++) {
                aP0[t] = __hfma2(ab,  hx[t], aP0[t]);    // {ΣAx, ΣBy}
                aQ0[t] = __hfma2(ba2, hx[t], aQ0[t]);    // {ΣBx, ΣAy}
            }
        }
        #pragma unroll
        for (int j = 16; j < 32; j++) {
            uint2 m = sABBA[j * 32 + lane];
            __half2 ab = *reinterpret_cast<__half2*>(&m.x);
            __half2 ba2 = *reinterpret_cast<__half2*>(&m.y);
            uint4 pxy = sXY[wib][q][j];
            const __half2* hx = reinterpret_cast<const __half2*>(&pxy);
            #pragma unroll
            for (int t = 0; t < 4; t++) {
                aP1[t] = __hfma2(ab,  hx[t], aP1[t]);
                aQ1[t] = __hfma2(ba2, hx[t], aQ1[t]);
            }
        }

        #pragma unroll
        for (int t = 0; t < 4; t++) {
            float2 p0 = __half22float2(aP0[t]);
            float2 p1 = __half22float2(aP1[t]);
            float2 q0 = __half22float2(aQ0[t]);
            float2 q1 = __half22float2(aQ1[t]);
            float P = (p0.x + p1.x) - (p0.y + p1.y);     // ΣAx - ΣBy
            float Q = (q0.x + q1.x) + (q0.y + q1.y);     // ΣBx + ΣAy
            int tt = q * 4 + t;
            out[(size_t)(rowBase + tt) * 96 + lane] = tpv + cv[tt] * P - sv[tt] * Q;
        }
    }
}

// ---------------- guarded tail kernel (remainder rows; unused at 65536) --------
__global__ void hopf_tail(const float* __restrict__ in, float* __restrict__ out,
                          int rowStart, int nrows) {
    const int tid  = threadIdx.x;
    const int lane = tid & 31;
    const int wib  = tid >> 5;

    __shared__ uint2 sABBA[1024];
    __shared__ uint4 sXY[8][2][32];

    {
        const float4* src = reinterpret_cast<const float4*>(gABBA);
        float4*       dst = reinterpret_cast<float4*>(sABBA);
        dst[tid]       = src[tid];
        dst[tid + 256] = src[tid + 256];
    }
    const float tpv = gTPV[lane];
    const float ba  = gBA[lane];
    const float ca  = gCA[lane];
    __syncthreads();

    const int rowBase = rowStart + wib * 8;

    float psi[8], rr[8], rd[8];
    #pragma unroll
    for (int t = 0; t < 8; t++) {
        const int row = rowBase + t;
        psi[t] = 0.0f;  rr[t] = 0.0f;  rd[t] = 0.0f;
        if (row < nrows) {
            const float* rp = in + (size_t)row * 96;
            psi[t] = rp[lane];  rr[t] = rp[32 + lane];  rd[t] = rp[64 + lane];
        }
    }

    float sv[8], cv[8];
    uint4 xy0, xy1;
    #pragma unroll
    for (int t = 0; t < 8; t++) {
        __sincosf(psi[t], &sv[t], &cv[t]);
        __half2 h = __floats2half2_rn(rr[t] * sv[t], rr[t] * cv[t]);
        if (t < 4) reinterpret_cast<__half2*>(&xy0)[t]     = h;
        else       reinterpret_cast<__half2*>(&xy1)[t - 4] = h;
        const int row = rowBase + t;
        if (row < nrows) {
            float rdd = ca * (0.25f * ca * (ba - rr[t]) - rd[t]);
            float* op = out + (size_t)row * 96;
            op[32 + lane] = rd[t];
            op[64 + lane] = rdd;
        }
    }
    sXY[wib][0][lane] = xy0;
    sXY[wib][1][lane] = xy1;
    __syncwarp();

    #pragma unroll
    for (int q = 0; q < 2; q++) {
        __half2 z = __floats2half2_rn(0.0f, 0.0f);
        __half2 aP0[4] = {z,z,z,z}, aP1[4] = {z,z,z,z};
        __half2 aQ0[4] = {z,z,z,z}, aQ1[4] = {z,z,z,z};

        #pragma unroll
        for (int j = 0; j < 16; j++) {
            uint2 m = sABBA[j * 32 + lane];
            __half2 ab = *reinterpret_cast<__half2*>(&m.x);
            __half2 ba2 = *reinterpret_cast<__half2*>(&m.y);
            uint4 pxy = sXY[wib][q][j];
            const __half2* hx = reinterpret_cast<const __half2*>(&pxy);
            #pragma unroll
            for (int t = 0; t < 4; t++) {
                aP0[t] = __hfma2(ab,  hx[t], aP0[t]);
                aQ0[t] = __hfma2(ba2, hx[t], aQ0[t]);
            }
        }
        #pragma unroll
        for (int j = 16; j < 32; j++) {
            uint2 m = sABBA[j * 32 + lane];
            __half2 ab = *reinterpret_cast<__half2*>(&m.x);
            __half2 ba2 = *reinterpret_cast<__half2*>(&m.y);
            uint4 pxy = sXY[wib][q][j];
            const __half2* hx = reinterpret_cast<const __half2*>(&pxy);
            #pragma unroll
            for (int t = 0; t < 4; t++) {
                aP1[t] = __hfma2(ab,  hx[t], aP1[t]);
                aQ1[t] = __hfma2(ba2, hx[t], aQ1[t]);
            }
        }

        #pragma unroll
        for (int t = 0; t < 4; t++) {
            const int tt = q * 4 + t;
            const int row = rowBase + tt;
            if (row < nrows) {
                float2 p0 = __half22float2(aP0[t]);
                float2 p1 = __half22float2(aP1[t]);
                float2 q0 = __half22float2(aQ0[t]);
                float2 q1 = __half22float2(aQ1[t]);
                float P = (p0.x + p1.x) - (p0.y + p1.y);
                float Q = (q0.x + q1.x) + (q0.y + q1.y);
                out[(size_t)row * 96 + lane] = tpv + cv[tt] * P - sv[tt] * Q;
            }
        }
    }
}

extern "C" void kernel_launch(void* const* d_in, const int* in_sizes, int n_in,
                              void* d_out, int out_size) {
    const float* states = (const float*)d_in[0];
    const float* v      = (const float*)d_in[1];
    const float* b      = (const float*)d_in[2];
    const float* c      = (const float*)d_in[3];
    const float* w      = (const float*)d_in[4];
    const float* phi    = (const float*)d_in[5];
    float* out = (float*)d_out;

    const int nrows = in_sizes[0] / 96;         // 65536
    prep_kernel<<<8, 128>>>(v, b, c, w, phi);

    const int fullBlocks = nrows / 64;          // 64 rows per 256-thread block
    if (fullBlocks > 0)
        hopf_kernel<<<fullBlocks, 256>>>(states, out);

    const int covered = fullBlocks * 64;
    if (covered < nrows)
        hopf_tail<<<1, 256>>>(states, out, covered, nrows);
}

// round 14
// speedup vs baseline: 1.5514x; 1.5514x over previous
#include <cuda_runtime.h>
#include <cuda_fp16.h>
#include <cstdint>

// Hopf oscillator CPG step, reformulated:
//   sin(psi_j - psi_i - phi_ij) = (s_j c_i - c_j s_i)cosφ - (c_j c_i + s_j s_i)sinφ
// A_ij = w_zd cosφ_zd, B_ij = w_zd sinφ_zd, x_j = r_j s_j, y_j = r_j c_j:
//   coupling_i = c_i*(A x - B y)_i - s_i*(A y + B x)_i
// R14 = R12 (21.0us, best) + ONLY the matrix-packing idea from R13:
//   uint2 {half2{A,B}, half2{B,A}} -> one LDS.64 feeds accP and accQ, and the
//   sYX mirror buffer is deleted (prologue: -4 cvt, -1 STS.128 per quad;
//   inner: 10 instr per quad-j).
// R13's whole-tile LDG hoist is REVERTED: it spilled (24+ extra live regs under
// the 64-reg cap -> 1.2 TB/s local-memory traffic, 21->29us). Two-quad live
// window stays, launch_bounds(256,5) as in R12.

#define PI2F 6.28318530717958647692f

__device__ uint2 gABBA[1024];   // [j*32 + i] = {half2{A,B}, half2{B,A}} (pre-transposed)
__device__ float gTPV[32];      // 2*pi*V_MAX*sigmoid(v)
__device__ float gBA[32];       // B_MAX*sigmoid(b)
__device__ float gCA[32];       // C_MAX*sigmoid(c)

__device__ __forceinline__ float fsigmoid(float x) {
    return 1.0f / (1.0f + __expf(-x));
}

__global__ void prep_kernel(const float* __restrict__ v, const float* __restrict__ b,
                            const float* __restrict__ c, const float* __restrict__ w,
                            const float* __restrict__ phi) {
    int m = blockIdx.x * 128 + threadIdx.x;   // 0..1023, m = i*32 + j
    float A = 0.0f, Bv = 0.0f;
    if (m % 33 != 0) {              // zero-diag: diagonal iff m % 33 == 0
        int kk = m / 33;            // 0..30
        int jj = m % 33 - 1;        // 0..31
        float wa = fsigmoid(w[kk * 32 + jj]);           // W_MAX = 1
        float pa = PI2F * fsigmoid(phi[kk * 32 + jj]);  // PHI_MAX = 2*pi
        float sp, cp;
        __sincosf(pa, &sp, &cp);
        A  = wa * cp;
        Bv = wa * sp;
    }
    __half2 ab = __floats2half2_rn(A, Bv);
    __half2 ba = __floats2half2_rn(Bv, A);
    gABBA[(m & 31) * 32 + (m >> 5)] =
        make_uint2(*reinterpret_cast<uint32_t*>(&ab), *reinterpret_cast<uint32_t*>(&ba));
    if (m < 32) {
        gTPV[m] = (PI2F * 5.0f) * fsigmoid(v[m]);
        gBA[m]  = 2.0f  * fsigmoid(b[m]);
        gCA[m]  = 10.0f * fsigmoid(c[m]);
    }
}

// ---------------- hot kernel: full 64-row tiles only, no guards ----------------
__global__ __launch_bounds__(256, 5)
void hopf_kernel(const float* __restrict__ in, float* __restrict__ out) {
    const int tid  = threadIdx.x;
    const int lane = tid & 31;          // oscillator index i
    const int wib  = tid >> 5;          // warp in block (0..7)

    __shared__ uint2 sABBA[1024];       // [j*32 + i] -> LDS.64
    __shared__ uint4 sXY[8][2][32];     // [warp][quad][j] = half2{x,y} rows 0..3

    // coalesced L2->smem copy of the prebuilt matrix (8KB, 2 float4/thread)
    {
        const float4* src = reinterpret_cast<const float4*>(gABBA);
        float4*       dst = reinterpret_cast<float4*>(sABBA);
        dst[tid]       = src[tid];
        dst[tid + 256] = src[tid + 256];
    }

    const float tpv = gTPV[lane];
    const float ba  = gBA[lane];
    const float ca  = gCA[lane];

    __syncthreads();

    const int rowBase = (blockIdx.x * 8 + wib) * 8;   // 8 rows per warp

    #pragma unroll
    for (int q = 0; q < 2; q++) {
        const int r0 = rowBase + q * 4;
        float sv[4], cv[4];
        uint4 xy;                        // 4 rows of half2{x,y}, built in regs

        #pragma unroll
        for (int t = 0; t < 4; t++) {
            const float* rp = in + (size_t)(r0 + t) * 96;
            float psi = rp[lane];
            float rr  = rp[32 + lane];
            float rd  = rp[64 + lane];
            __sincosf(psi, &sv[t], &cv[t]);
            reinterpret_cast<__half2*>(&xy)[t] =
                __floats2half2_rn(rr * sv[t], rr * cv[t]);   // {x,y}
            float rdd = ca * (0.25f * ca * (ba - rr) - rd);
            float* op = out + (size_t)(r0 + t) * 96;
            op[32 + lane] = rd;
            op[64 + lane] = rdd;
        }

        __syncwarp();   // previous quad's readers done before overwrite
        sXY[wib][q][lane] = xy;          // 1 STS.128
        __syncwarp();

        // split half2 accumulators: [t] over 4 rows; 0 = j<16, 1 = j>=16
        __half2 z = __floats2half2_rn(0.0f, 0.0f);
        __half2 aP0[4] = {z,z,z,z}, aP1[4] = {z,z,z,z};
        __half2 aQ0[4] = {z,z,z,z}, aQ1[4] = {z,z,z,z};

        #pragma unroll
        for (int j = 0; j < 16; j++) {
            uint2 m = sABBA[j * 32 + lane];              // LDS.64 {AB, BA}
            __half2 ab  = *reinterpret_cast<__half2*>(&m.x);
            __half2 ba2 = *reinterpret_cast<__half2*>(&m.y);
            uint4 pxy = sXY[wib][q][j];                  // broadcast LDS.128
            const __half2* hx = reinterpret_cast<const __half2*>(&pxy);
            #pragma unroll
            for (int t = 0; t < 4; t++) {
                aP0[t] = __hfma2(ab,  hx[t], aP0[t]);    // {ΣAx, ΣBy}
                aQ0[t] = __hfma2(ba2, hx[t], aQ0[t]);    // {ΣBx, ΣAy}
            }
        }
        #pragma unroll
        for (int j = 16; j < 32; j++) {
            uint2 m = sABBA[j * 32 + lane];
            __half2 ab  = *reinterpret_cast<__half2*>(&m.x);
            __half2 ba2 = *reinterpret_cast<__half2*>(&m.y);
            uint4 pxy = sXY[wib][q][j];
            const __half2* hx = reinterpret_cast<const __half2*>(&pxy);
            #pragma unroll
            for (int t = 0; t < 4; t++) {
                aP1[t] = __hfma2(ab,  hx[t], aP1[t]);
                aQ1[t] = __hfma2(ba2, hx[t], aQ1[t]);
            }
        }

        #pragma unroll
        for (int t = 0; t < 4; t++) {
            float2 p0 = __half22float2(aP0[t]);
            float2 p1 = __half22float2(aP1[t]);
            float2 q0 = __half22float2(aQ0[t]);
            float2 q1 = __half22float2(aQ1[t]);
            float P = (p0.x + p1.x) - (p0.y + p1.y);     // ΣAx - ΣBy
            float Q = (q0.x + q1.x) + (q0.y + q1.y);     // ΣBx + ΣAy
            out[(size_t)(r0 + t) * 96 + lane] = tpv + cv[t] * P - sv[t] * Q;
        }
    }
}

// ---------------- guarded tail kernel (remainder rows; unused at 65536) --------
__global__ void hopf_tail(const float* __restrict__ in, float* __restrict__ out,
                          int rowStart, int nrows) {
    const int tid  = threadIdx.x;
    const int lane = tid & 31;
    const int wib  = tid >> 5;

    __shared__ uint2 sABBA[1024];
    __shared__ uint4 sXY[8][2][32];

    {
        const float4* src = reinterpret_cast<const float4*>(gABBA);
        float4*       dst = reinterpret_cast<float4*>(sABBA);
        dst[tid]       = src[tid];
        dst[tid + 256] = src[tid + 256];
    }
    const float tpv = gTPV[lane];
    const float ba  = gBA[lane];
    const float ca  = gCA[lane];
    __syncthreads();

    const int rowBase = rowStart + wib * 8;

    #pragma unroll
    for (int q = 0; q < 2; q++) {
        const int r0 = rowBase + q * 4;
        float sv[4], cv[4];
        uint4 xy;

        #pragma unroll
        for (int t = 0; t < 4; t++) {
            const int row = r0 + t;
            float psi = 0.0f, rr = 0.0f, rd = 0.0f;
            if (row < nrows) {
                const float* rp = in + (size_t)row * 96;
                psi = rp[lane];  rr = rp[32 + lane];  rd = rp[64 + lane];
            }
            __sincosf(psi, &sv[t], &cv[t]);
            reinterpret_cast<__half2*>(&xy)[t] =
                __floats2half2_rn(rr * sv[t], rr * cv[t]);
            if (row < nrows) {
                float rdd = ca * (0.25f * ca * (ba - rr) - rd);
                float* op = out + (size_t)row * 96;
                op[32 + lane] = rd;
                op[64 + lane] = rdd;
            }
        }

        __syncwarp();
        sXY[wib][q][lane] = xy;
        __syncwarp();

        __half2 z = __floats2half2_rn(0.0f, 0.0f);
        __half2 aP0[4] = {z,z,z,z}, aP1[4] = {z,z,z,z};
        __half2 aQ0[4] = {z,z,z,z}, aQ1[4] = {z,z,z,z};

        #pragma unroll
        for (int j = 0; j < 16; j++) {
            uint2 m = sABBA[j * 32 + lane];
            __half2 ab  = *reinterpret_cast<__half2*>(&m.x);
            __half2 ba2 = *reinterpret_cast<__half2*>(&m.y);
            uint4 pxy = sXY[wib][q][j];
            const __half2* hx = reinterpret_cast<const __half2*>(&pxy);
            #pragma unroll
            for (int t = 0; t < 4; t++) {
                aP0[t] = __hfma2(ab,  hx[t], aP0[t]);
                aQ0[t] = __hfma2(ba2, hx[t], aQ0[t]);
            }
        }
        #pragma unroll
        for (int j = 16; j < 32; j++) {
            uint2 m = sABBA[j * 32 + lane];
            __half2 ab  = *reinterpret_cast<__half2*>(&m.x);
            __half2 ba2 = *reinterpret_cast<__half2*>(&m.y);
            uint4 pxy = sXY[wib][q][j];
            const __half2* hx = reinterpret_cast<const __half2*>(&pxy);
            #pragma unroll
            for (int t = 0; t < 4; t++) {
                aP1[t] = __hfma2(ab,  hx[t], aP1[t]);
                aQ1[t] = __hfma2(ba2, hx[t], aQ1[t]);
            }
        }

        #pragma unroll
        for (int t = 0; t < 4; t++) {
            const int row = r0 + t;
            if (row < nrows) {
                float2 p0 = __half22float2(aP0[t]);
                float2 p1 = __half22float2(aP1[t]);
                float2 q0 = __half22float2(aQ0[t]);
                float2 q1 = __half22float2(aQ1[t]);
                float P = (p0.x + p1.x) - (p0.y + p1.y);
                float Q = (q0.x + q1.x) + (q0.y + q1.y);
                out[(size_t)row * 96 + lane] = tpv + cv[t] * P - sv[t] * Q;
            }
        }
    }
}

extern "C" void kernel_launch(void* const* d_in, const int* in_sizes, int n_in,
                              void* d_out, int out_size) {
    const float* states = (const float*)d_in[0];
    const float* v      = (const float*)d_in[1];
    const float* b      = (const float*)d_in[2];
    const float* c      = (const float*)d_in[3];
    const float* w      = (const float*)d_in[4];
    const float* phi    = (const float*)d_in[5];
    float* out = (float*)d_out;

    const int nrows = in_sizes[0] / 96;         // 65536
    prep_kernel<<<8, 128>>>(v, b, c, w, phi);

    const int fullBlocks = nrows / 64;          // 64 rows per 256-thread block
    if (fullBlocks > 0)
        hopf_kernel<<<fullBlocks, 256>>>(states, out);

    const int covered = fullBlocks * 64;
    if (covered < nrows)
        hopf_tail<<<1, 256>>>(states, out, covered, nrows);
}